// round 17
// baseline (speedup 1.0000x reference)
#include <cuda_runtime.h>
#include <cuda_fp16.h>
#include <cstdint>

// out = tanh(x @ W^T + b); x (131072, 256) fp32, W (256,256) fp32, b (256).
//
// mma.sync m16n8k16 f16->f32 (compute_103-portable).
// Round-17: classic two-operand SMEM GEMM, 512 threads / 16 warps / CTA,
// persistent 148 CTAs. W converted once to fp16 SMEM (128KB, ldmatrix
// swizzle); BOTH A (x tile) and B (W) frags via ldmatrix. One ldsm.x4 over
// 16 W-rows yields B-frags for TWO n-atoms ({r0,r2},{r1,r3}) — dual of the
// A-frag layout. Warp tile m32 x n32 (grid 2 m-rows x 8 n-cols), MT=64.
// ~110 regs/thread -> 4 warps/SMSP (the latency coverage r5 lacked), no
// spills (the r8 failure). Fill: direct LDG->cvt->swizzled STS woven into
// the ks loop (distance-4 batches). Single __syncthreads per iter.

#define HID      256
#define MT       64
#define NT       2048
#define GRID     148
#define NTHREADS 512

// SMEM (bytes): W fp16 128KB, two x fp16 bufs 32KB each = 192KB
#define SM_W     0u
#define SM_B0    131072u
#define SM_B1    163840u
#define SMEM_TOTAL 196608

// ---------------------------------------------------------------- helpers ----

__device__ __forceinline__ uint32_t smem_u32(const void* p) {
    uint32_t a;
    asm("{ .reg .u64 t; cvta.to.shared.u64 t, %1; cvt.u32.u64 %0, t; }"
        : "=r"(a) : "l"(p));
    return a;
}

__device__ __forceinline__ void sts64(uint32_t addr, uint32_t a, uint32_t b) {
    asm volatile("st.shared.v2.u32 [%0], {%1, %2};" :: "r"(addr), "r"(a), "r"(b));
}

__device__ __forceinline__ void ldsm_x4(uint32_t* r, uint32_t addr) {
    asm volatile("ldmatrix.sync.aligned.m8n8.x4.shared.b16 {%0, %1, %2, %3}, [%4];"
                 : "=r"(r[0]), "=r"(r[1]), "=r"(r[2]), "=r"(r[3]) : "r"(addr));
}

__device__ __forceinline__ void mma16816(float* d, const uint32_t* a,
                                         uint32_t b0, uint32_t b1) {
    asm volatile(
        "mma.sync.aligned.m16n8k16.row.col.f32.f16.f16.f32 "
        "{%0, %1, %2, %3}, {%4, %5, %6, %7}, {%8, %9}, {%0, %1, %2, %3};"
        : "+f"(d[0]), "+f"(d[1]), "+f"(d[2]), "+f"(d[3])
        : "r"(a[0]), "r"(a[1]), "r"(a[2]), "r"(a[3]), "r"(b0), "r"(b1));
}

__device__ __forceinline__ float tanh_f(float y) {
    float r;
    asm("tanh.approx.f32 %0, %1;" : "=f"(r) : "f"(y));
    return r;
}

// convert one float4 -> fp16 swizzled slot for float4-index g (row = g>>6)
__device__ __forceinline__ void cvt_store(uint32_t dst, int g, float4 v) {
    __half2 h0 = __floats2half2_rn(v.x, v.y);
    __half2 h1 = __floats2half2_rn(v.z, v.w);
    uint32_t row = (uint32_t)(g >> 6);        // 64 float4 per 256-col row
    uint32_t c4  = (uint32_t)(g & 63);
    uint32_t c16 = c4 >> 1;
    uint32_t a = dst + row * 512u + ((c16 ^ (row & 7u)) << 4) + (c4 & 1u) * 8u;
    sts64(a, *(const uint32_t*)&h0, *(const uint32_t*)&h1);
}

// swizzled ldsm address for a 16-row block starting at row0, k-chunk base c0
__device__ __forceinline__ uint32_t frag_addr(uint32_t buf, uint32_t row0,
                                              uint32_t c0, int l) {
    uint32_t row = row0 + (uint32_t)(l & 15);
    uint32_t c16 = c0 + (uint32_t)(l >> 4);
    return buf + row * 512u + ((c16 ^ (row & 7u)) << 4);
}

// ----------------------------------------------------------------- kernel ----

__global__ void __launch_bounds__(NTHREADS, 1)
rotor_kernel(const float* __restrict__ x, const float* __restrict__ W,
             const float* __restrict__ b, float* __restrict__ out) {
    extern __shared__ char smem[];
    const uint32_t sb = smem_u32(smem);
    const int tid = threadIdx.x;
    const int w = tid >> 5;
    const int l = tid & 31;
    const int mw = w >> 3;       // m-row: tokens [mw*32, mw*32+32)
    const int nw = w & 7;        // n-col: cols [nw*32, nw*32+32)

    const int t0 = blockIdx.x;

    // --- prologue: W (fp32) -> fp16 SMEM, rows = n, same swizzle as x tiles
    {
        const float4* Wv = (const float4*)W;
#pragma unroll
        for (int i = 0; i < 32; i++) {
            int g = tid + i * NTHREADS;          // 0..16383
            cvt_store(sb + SM_W, g, Wv[g]);
        }
    }
    // --- prologue: x tile t0 -> buf0
    {
        const float4* src = (const float4*)(x + (size_t)t0 * MT * HID);
#pragma unroll
        for (int i = 0; i < 8; i++) {
            int g = tid + i * NTHREADS;          // 0..4095
            cvt_store(sb + SM_B0, g, src[g]);
        }
    }

    // bias for this thread's output columns (frag layout)
    float2 bb[4];
#pragma unroll
    for (int na = 0; na < 4; na++)
        bb[na] = *(const float2*)&b[nw * 32 + na * 8 + (l & 3) * 2];

    int iter = 0;
    for (int t = t0; t < NT; t += GRID, iter++) {
        const uint32_t bufg = sb + ((iter & 1) ? SM_B1 : SM_B0);   // GEMM src
        const uint32_t bufc = sb + ((iter & 1) ? SM_B0 : SM_B1);   // cvt dst
        const bool have_next = (t + GRID) < NT;
        const float4* nsrc = (const float4*)(x + (size_t)(t + GRID) * MT * HID);

        // Single barrier: orders prev STS of bufg before this iter's ldsm,
        // prev ldsm of bufc before this iter's STS (and prologue on iter 0).
        __syncthreads();

        float acc[2][4][4];
#pragma unroll
        for (int ma = 0; ma < 2; ma++)
#pragma unroll
            for (int na = 0; na < 4; na++)
#pragma unroll
                for (int c = 0; c < 4; c++) acc[ma][na][c] = 0.0f;

        // frag double buffers: fa[set][ma][4], fb[set][pair][4]
        uint32_t fa[2][2][4], fb[2][2][4];
        {
#pragma unroll
            for (int ma = 0; ma < 2; ma++)
                ldsm_x4(fa[0][ma],
                        frag_addr(bufg, (uint32_t)(mw * 32 + ma * 16), 0u, l));
#pragma unroll
            for (int p = 0; p < 2; p++)
                ldsm_x4(fb[0][p],
                        frag_addr(sb + SM_W, (uint32_t)(nw * 32 + p * 16), 0u, l));
        }

        // fill weave: 8 batches of 1 float4/thread; LDG batch k at ks=k
        // (k=0..7), cvt batch k at ks=k+4 (4..11). Slot k&3: read-before-
        // overwrite within the same step (sequential semantics).
        float4 xb[4];

#pragma unroll
        for (int ks = 0; ks < 16; ks++) {
            const int s = ks & 1, sn = s ^ 1;
            if (ks < 15) {
                const uint32_t c0 = (uint32_t)((ks + 1) * 2);
#pragma unroll
                for (int ma = 0; ma < 2; ma++)
                    ldsm_x4(fa[sn][ma],
                            frag_addr(bufg, (uint32_t)(mw * 32 + ma * 16), c0, l));
#pragma unroll
                for (int p = 0; p < 2; p++)
                    ldsm_x4(fb[sn][p],
                            frag_addr(sb + SM_W, (uint32_t)(nw * 32 + p * 16), c0, l));
            }
            if (have_next) {
                if (ks >= 4 && ks < 12)
                    cvt_store(bufc, tid + (ks - 4) * NTHREADS, xb[(ks - 4) & 3]);
                if (ks < 8)
                    xb[ks & 3] = nsrc[tid + ks * NTHREADS];
            }
#pragma unroll
            for (int ma = 0; ma < 2; ma++)
#pragma unroll
                for (int na = 0; na < 4; na++)
                    mma16816(acc[ma][na], fa[s][ma],
                             fb[s][na >> 1][na & 1], fb[s][na >> 1][(na & 1) + 2]);
        }

        // --- epilogue: tanh(acc + b) -> out (frag-layout float2 stores)
        const size_t r0 = (size_t)t * MT + mw * 32 + (l >> 2);
        const int n0 = nw * 32 + (l & 3) * 2;
#pragma unroll
        for (int ma = 0; ma < 2; ma++) {
            const size_t rr = r0 + ma * 16;
#pragma unroll
            for (int na = 0; na < 4; na++) {
                float2 v0, v1;
                v0.x = tanh_f(acc[ma][na][0] + bb[na].x);
                v0.y = tanh_f(acc[ma][na][1] + bb[na].y);
                v1.x = tanh_f(acc[ma][na][2] + bb[na].x);
                v1.y = tanh_f(acc[ma][na][3] + bb[na].y);
                __stcs((float2*)&out[rr * HID + n0 + na * 8], v0);
                __stcs((float2*)&out[(rr + 8) * HID + n0 + na * 8], v1);
            }
        }
    }
}

// ----------------------------------------------------------------- launch ----

extern "C" void kernel_launch(void* const* d_in, const int* in_sizes, int n_in,
                              void* d_out, int out_size) {
    const float* x = (const float*)d_in[0];
    const float* W = (const float*)d_in[1];
    const float* b = (const float*)d_in[2];
    float* out = (float*)d_out;
    cudaFuncSetAttribute(rotor_kernel,
                         cudaFuncAttributeMaxDynamicSharedMemorySize, SMEM_TOTAL);
    rotor_kernel<<<GRID, NTHREADS, SMEM_TOTAL>>>(x, W, b, out);
}